// round 5
// baseline (speedup 1.0000x reference)
#include <cuda_runtime.h>
#include <cuda_bf16.h>
#include <math.h>
#include <stdint.h>

// ---------------- static problem shape ----------------
#define BATCH 32
#define IMGH  56
#define IMGW  56
#define CCH   192
#define LLEN  (IMGH*IMGW)        // 3136
#define NHEAD 6
#define HDIM  32
#define WSZ   7
#define SHIFT_ 3
#define LW    49
#define NWIN  64
#define NWTOT (BATCH*NWIN)       // 2048
#define MTOK  (BATCH*LLEN)       // 100352

// ---------------- scratch ----------------
__device__ __nv_bfloat16 g_qkv [(size_t)MTOK*3*CCH];
__device__ __nv_bfloat16 g_attn[(size_t)MTOK*CCH];
__device__ __nv_bfloat16 g_h1  [(size_t)MTOK*4*CCH];
__device__ float g_xres[(size_t)MTOK*CCH];
__device__ float g_st1 [(size_t)MTOK*2];
__device__ float g_st2 [(size_t)MTOK*2];

__device__ __forceinline__ float gelu_exact(float x) {
    return 0.5f * x * (1.0f + erff(x * 0.70710678118654752f));
}
__device__ __forceinline__ uint32_t pack_bf16x2(float lo, float hi) {
    uint32_t o;
    asm("cvt.rn.bf16x2.f32 %0, %1, %2;" : "=r"(o) : "f"(hi), "f"(lo));
    return o;
}
__device__ __forceinline__ void mma_bf16(float c[4], const uint32_t a[4], const uint32_t b[2]) {
    asm volatile(
        "mma.sync.aligned.m16n8k16.row.col.f32.bf16.bf16.f32 "
        "{%0,%1,%2,%3}, {%4,%5,%6,%7}, {%8,%9}, {%0,%1,%2,%3};"
        : "+f"(c[0]), "+f"(c[1]), "+f"(c[2]), "+f"(c[3])
        : "r"(a[0]), "r"(a[1]), "r"(a[2]), "r"(a[3]), "r"(b[0]), "r"(b[1]));
}

__device__ __forceinline__ int winrow_to_token(int wr) {
    const int w  = wr / LW, local = wr % LW;
    const int b  = w >> 6, wl = w & 63;
    const int hp = (wl >> 3)*WSZ + local/WSZ;
    const int wp = (wl & 7)*WSZ + local%WSZ;
    int h = hp + SHIFT_; if (h >= IMGH) h -= IMGH;
    int ww = wp + SHIFT_; if (ww >= IMGW) ww -= IMGW;
    return b*LLEN + h*IMGW + ww;
}

// ---------------- LN stats: one warp per token ----------------
__global__ void __launch_bounds__(256)
ln_stats_kernel(const float* __restrict__ in, float* __restrict__ stats)
{
    const int warp = (blockIdx.x * 256 + threadIdx.x) >> 5;
    const int lane = threadIdx.x & 31;
    if (warp >= MTOK) return;
    const float* p = in + (size_t)warp*CCH;
    float s = 0.f, s2 = 0.f;
    #pragma unroll
    for (int i = 0; i < 6; ++i) {
        const float v = p[lane + i*32];
        s += v; s2 += v*v;
    }
    #pragma unroll
    for (int off = 16; off > 0; off >>= 1) {
        s  += __shfl_down_sync(0xffffffff, s,  off);
        s2 += __shfl_down_sync(0xffffffff, s2, off);
    }
    if (lane == 0) {
        const float mean = s * (1.0f/CCH);
        const float var  = s2 * (1.0f/CCH) - mean*mean;
        stats[2*warp]   = mean;
        stats[2*warp+1] = rsqrtf(var + 1e-5f);
    }
}

// ---------------- BF16 TC GEMM, fused LN/gather A-ops and fused epilogues ----
// AOP: 0=plain, 1=LN(A), 2=LN(A)+window-gather rows   (AOP!=0 requires fp32 A)
// ACT: 0=none, 1=gelu
// WOP: 0=plain, 1=scatter rows + add residual
// A_BF: A operand stored as bf16  |  O_BF: output written as bf16
#define RS 20
#define ABUF (128*RS)
#define BBUF (64*RS)
template<int AOP, int ACT, bool HAS_BIAS, bool HAS_RES, int WOP, bool A_BF, bool O_BF>
__global__ void __launch_bounds__(256)
gemm_tc(const void* __restrict__ Av, const float* __restrict__ W,
        const float* __restrict__ bias, const float* __restrict__ res,
        const float* __restrict__ stats,
        const float* __restrict__ gamma, const float* __restrict__ beta,
        void* __restrict__ outv, int M, int N, int K)
{
    const float* Af = (const float*)Av;
    const __nv_bfloat16* Ab = (const __nv_bfloat16*)Av;
    float* outf = (float*)outv;
    __nv_bfloat16* outb = (__nv_bfloat16*)outv;

    const int tid  = threadIdx.x;
    const int lane = tid & 31;
    const int warp = tid >> 5;
    const int warpM = warp & 3;
    const int warpN = warp >> 2;
    const int m0 = blockIdx.y * 128;
    const int n0 = blockIdx.x * 64;

    __shared__ uint32_t sA[2*ABUF];
    __shared__ uint32_t sB[2*BBUF];

    float acc[2][4][4];
    #pragma unroll
    for (int i = 0; i < 2; ++i)
        #pragma unroll
        for (int j = 0; j < 4; ++j)
            #pragma unroll
            for (int q = 0; q < 4; ++q) acc[i][j][q] = 0.f;

    const int aK4 = (tid & 7) << 2;   // element offset within 32-k tile
    const int kw0 = (tid & 7) << 1;   // word offset within 16
    const int aR0 = tid >> 3;
    const int laneR = lane >> 2;
    const int laneK = lane & 3;
    uint32_t* baseA = &sA[(warpM*32 + laneR)*RS + laneK];
    uint32_t* baseB = &sB[(warpN*32 + laneR)*RS + laneK];

    int aSrc[4];
    float aMean[4], aRstd[4];
    #pragma unroll
    for (int r = 0; r < 4; ++r) {
        const int wr = m0 + aR0 + r*32;
        aSrc[r] = (AOP == 2) ? winrow_to_token(wr) : wr;
        if (AOP != 0) {
            aMean[r] = stats[2*aSrc[r]];
            aRstd[r] = stats[2*aSrc[r]+1];
        }
    }

    float4 ra4[4];
    uint2  rab[4];
    float4 rb[2];

    #define LOAD_A(k0)                                                           \
    {                                                                            \
        _Pragma("unroll")                                                        \
        for (int r = 0; r < 4; ++r) {                                            \
            if (A_BF) rab[r] = *reinterpret_cast<const uint2*>(                  \
                                   &Ab[(size_t)aSrc[r]*K + (k0) + aK4]);         \
            else      ra4[r] = *reinterpret_cast<const float4*>(                 \
                                   &Af[(size_t)aSrc[r]*K + (k0) + aK4]);         \
        }                                                                        \
    }
    #define LOAD_B(k0)                                                           \
    {                                                                            \
        _Pragma("unroll")                                                        \
        for (int r = 0; r < 2; ++r)                                              \
            rb[r] = *reinterpret_cast<const float4*>(                            \
                        &W[(size_t)(n0 + aR0 + r*32)*K + (k0) + aK4]);           \
    }
    #define STORE_TILE(stage, koff)                                              \
    {                                                                            \
        float4 gm4, bt4;                                                         \
        if (AOP != 0) {                                                          \
            gm4 = *reinterpret_cast<const float4*>(&gamma[(koff) + aK4]);        \
            bt4 = *reinterpret_cast<const float4*>(&beta [(koff) + aK4]);        \
        }                                                                        \
        _Pragma("unroll")                                                        \
        for (int r = 0; r < 4; ++r) {                                            \
            uint32_t* p = &sA[(stage)*ABUF + (aR0 + r*32)*RS + kw0];             \
            if (A_BF) {                                                          \
                p[0] = rab[r].x; p[1] = rab[r].y;                                \
            } else {                                                             \
                float vx = ra4[r].x, vy = ra4[r].y, vz = ra4[r].z, vw = ra4[r].w;\
                if (AOP != 0) {                                                  \
                    vx = (vx - aMean[r])*aRstd[r]*gm4.x + bt4.x;                 \
                    vy = (vy - aMean[r])*aRstd[r]*gm4.y + bt4.y;                 \
                    vz = (vz - aMean[r])*aRstd[r]*gm4.z + bt4.z;                 \
                    vw = (vw - aMean[r])*aRstd[r]*gm4.w + bt4.w;                 \
                }                                                                \
                p[0] = pack_bf16x2(vx, vy);                                      \
                p[1] = pack_bf16x2(vz, vw);                                      \
            }                                                                    \
        }                                                                        \
        _Pragma("unroll")                                                        \
        for (int r = 0; r < 2; ++r) {                                            \
            uint32_t* p = &sB[(stage)*BBUF + (aR0 + r*32)*RS + kw0];             \
            p[0] = pack_bf16x2(rb[r].x, rb[r].y);                                \
            p[1] = pack_bf16x2(rb[r].z, rb[r].w);                                \
        }                                                                        \
    }

    LOAD_A(0)
    LOAD_B(0)
    STORE_TILE(0, 0)

    const int ntiles = K >> 5;
    for (int t = 0; t < ntiles; ++t) {
        __syncthreads();
        const bool more = (t + 1 < ntiles);
        if (more) {
            const int k0 = (t+1) << 5;
            LOAD_A(k0)
            LOAD_B(k0)
        }

        const uint32_t* pA = baseA + (t & 1)*ABUF;
        const uint32_t* pB = baseB + (t & 1)*BBUF;
        #pragma unroll
        for (int ks = 0; ks < 2; ++ks) {
            uint32_t af[2][4], bf[4][2];
            #pragma unroll
            for (int mt = 0; mt < 2; ++mt) {
                const uint32_t* q = pA + mt*(16*RS) + ks*8;
                af[mt][0] = q[0];
                af[mt][1] = q[8*RS];
                af[mt][2] = q[4];
                af[mt][3] = q[8*RS + 4];
            }
            #pragma unroll
            for (int nt = 0; nt < 4; ++nt) {
                const uint32_t* q = pB + nt*(8*RS) + ks*8;
                bf[nt][0] = q[0];
                bf[nt][1] = q[4];
            }
            #pragma unroll
            for (int mt = 0; mt < 2; ++mt)
                #pragma unroll
                for (int nt = 0; nt < 4; ++nt)
                    mma_bf16(acc[mt][nt], af[mt], bf[nt]);
        }

        if (more) {
            const int st = (t + 1) & 1;
            const int k0u = (t+1) << 5;
            STORE_TILE(st, k0u)
        }
    }
    #undef LOAD_A
    #undef LOAD_B
    #undef STORE_TILE

    // epilogue
    #pragma unroll
    for (int mt = 0; mt < 2; ++mt) {
        #pragma unroll
        for (int nt = 0; nt < 4; ++nt) {
            const int col = n0 + warpN*32 + nt*8 + (laneK << 1);
            const float b0 = HAS_BIAS ? bias[col]   : 0.f;
            const float b1 = HAS_BIAS ? bias[col+1] : 0.f;
            #pragma unroll
            for (int half = 0; half < 2; ++half) {
                const int wr = m0 + warpM*32 + mt*16 + laneR + half*8;
                const int row = (WOP == 1) ? winrow_to_token(wr) : wr;
                float v0 = acc[mt][nt][half*2+0] + b0;
                float v1 = acc[mt][nt][half*2+1] + b1;
                if (ACT == 1) { v0 = gelu_exact(v0); v1 = gelu_exact(v1); }
                if (HAS_RES || WOP == 1) {
                    const float2 r2 = *reinterpret_cast<const float2*>(&res[(size_t)row*N + col]);
                    v0 += r2.x; v1 += r2.y;
                }
                if (O_BF) {
                    *reinterpret_cast<uint32_t*>(&outb[(size_t)row*N + col]) = pack_bf16x2(v0, v1);
                } else {
                    *reinterpret_cast<float2*>(&outf[(size_t)row*N + col]) = make_float2(v0, v1);
                }
            }
        }
    }
}

// ---------------- fused attention per (window, head) ----------------
__device__ __forceinline__ int regid(int p) { return (p < 49) ? 0 : ((p < 53) ? 1 : 2); }

__global__ void __launch_bounds__(128)
attn_kernel(const float* __restrict__ rel_bias)
{
    const int h = blockIdx.x;
    const int w = blockIdx.y;
    const int tid = threadIdx.x;

    __shared__ float sQ[LW*33];
    __shared__ float sK[LW*33];
    __shared__ float sV[LW*32];
    __shared__ float sS[LW*LW];

    for (int t = tid; t < LW*HDIM; t += 128) {
        const int i = t >> 5, d = t & 31;
        const size_t base = (size_t)(w*LW + i) * (3*CCH);
        sQ[i*33 + d] = __bfloat162float(g_qkv[base + h*HDIM + d]);
        sK[i*33 + d] = __bfloat162float(g_qkv[base + CCH + h*HDIM + d]);
        sV[i*32 + d] = __bfloat162float(g_qkv[base + 2*CCH + h*HDIM + d]);
    }
    __syncthreads();

    const int wl  = w & (NWIN-1);
    const int wh_ = wl >> 3, ww_ = wl & 7;
    for (int t = tid; t < LW*LW; t += 128) {
        const int i = t / LW, j = t % LW;
        const int ih = i / WSZ, iw = i % WSZ;
        const int jh = j / WSZ, jw = j % WSZ;
        const int idi = regid(wh_*WSZ + ih)*3 + regid(ww_*WSZ + iw);
        const int idj = regid(wh_*WSZ + jh)*3 + regid(ww_*WSZ + jw);
        float sval;
        if (idi != idj) {
            sval = -100.0f;
        } else {
            float acc = 0.f;
            #pragma unroll
            for (int d = 0; d < HDIM; ++d)
                acc += sQ[i*33 + d] * sK[j*33 + d];
            const int bidx = ((ih - jh + 6)*13 + (iw - jw + 6));
            sval = acc * 13.856406460551018f + rel_bias[bidx*NHEAD + h];
        }
        sS[i*LW + j] = sval;
    }
    __syncthreads();

    if (tid < LW) {
        float mx = -1e30f;
        #pragma unroll
        for (int j = 0; j < LW; ++j) mx = fmaxf(mx, sS[tid*LW + j]);
        float sum = 0.f;
        #pragma unroll
        for (int j = 0; j < LW; ++j) {
            const float e = expf(sS[tid*LW + j] - mx);
            sS[tid*LW + j] = e;
            sum += e;
        }
        const float inv = 1.0f / sum;
        #pragma unroll
        for (int j = 0; j < LW; ++j) sS[tid*LW + j] *= inv;
    }
    __syncthreads();

    for (int t = tid; t < LW*HDIM; t += 128) {
        const int i = t >> 5, d = t & 31;
        float acc = 0.f;
        #pragma unroll
        for (int j = 0; j < LW; ++j)
            acc += sS[i*LW + j] * sV[j*32 + d];
        g_attn[(size_t)(w*LW + i)*CCH + h*HDIM + d] = __float2bfloat16(acc);
    }
}

// ---------------- launch ----------------
extern "C" void kernel_launch(void* const* d_in, const int* in_sizes, int n_in,
                              void* d_out, int out_size)
{
    const void* arr[20];
    int na = 0;
    for (int i = 0; i < n_in && na < 20; ++i)
        if (in_sizes[i] != 1) arr[na++] = d_in[i];
    const float* x     = (const float*)arr[0];
    const float* n1w   = (const float*)arr[3];
    const float* n1b   = (const float*)arr[4];
    const float* qkvw  = (const float*)arr[5];
    const float* relb  = (const float*)arr[6];
    const float* projw = (const float*)arr[7];
    const float* projb = (const float*)arr[8];
    const float* n2w   = (const float*)arr[9];
    const float* n2b   = (const float*)arr[10];
    const float* fc1w  = (const float*)arr[11];
    const float* fc1b  = (const float*)arr[12];
    const float* fc2w  = (const float*)arr[13];
    const float* fc2b  = (const float*)arr[14];
    float* out = (float*)d_out;

    void* p_qkv;  cudaGetSymbolAddress(&p_qkv,  g_qkv);
    void* p_attn; cudaGetSymbolAddress(&p_attn, g_attn);
    void* p_h1;   cudaGetSymbolAddress(&p_h1,   g_h1);
    float* p_xres; cudaGetSymbolAddress((void**)&p_xres, g_xres);
    float* p_st1;  cudaGetSymbolAddress((void**)&p_st1,  g_st1);
    float* p_st2;  cudaGetSymbolAddress((void**)&p_st2,  g_st2);

    // 1) LN1 stats
    ln_stats_kernel<<<MTOK/8, 256>>>(x, p_st1);

    // 2) QKV GEMM: fused LN1 + gather, bf16 out
    gemm_tc<2, 0, false, false, 0, false, true><<<dim3(576/64, MTOK/128), 256>>>(
        x, qkvw, nullptr, nullptr, p_st1, n1w, n1b, p_qkv, MTOK, 3*CCH, CCH);

    // 3) fused windowed attention (bf16 in/out)
    attn_kernel<<<dim3(NHEAD, NWTOT), 128>>>(relb);

    // 4) proj GEMM: bf16 A, + bias + scatter + residual(x) -> fp32 g_xres
    gemm_tc<0, 0, true, false, 1, true, false><<<dim3(192/64, MTOK/128), 256>>>(
        p_attn, projw, projb, x, nullptr, nullptr, nullptr, p_xres, MTOK, CCH, CCH);

    // 5) LN2 stats
    ln_stats_kernel<<<MTOK/8, 256>>>(p_xres, p_st2);

    // 6) fc1 GEMM: fused LN2, + bias + gelu, bf16 out
    gemm_tc<1, 1, true, false, 0, false, true><<<dim3(768/64, MTOK/128), 256>>>(
        p_xres, fc1w, fc1b, nullptr, p_st2, n2w, n2b, p_h1, MTOK, 4*CCH, CCH);

    // 7) fc2 GEMM: bf16 A, + bias + gelu (quirk) + residual -> d_out
    gemm_tc<0, 1, true, true, 0, true, false><<<dim3(192/64, MTOK/128), 256>>>(
        p_h1, fc2w, fc2b, p_xres, nullptr, nullptr, nullptr, out, MTOK, CCH, 4*CCH);

    (void)out_size;
}

// round 6
// speedup vs baseline: 1.5638x; 1.5638x over previous
#include <cuda_runtime.h>
#include <cuda_bf16.h>
#include <math.h>
#include <stdint.h>

// ---------------- static problem shape ----------------
#define BATCH 32
#define IMGH  56
#define IMGW  56
#define CCH   192
#define LLEN  (IMGH*IMGW)        // 3136
#define NHEAD 6
#define HDIM  32
#define WSZ   7
#define SHIFT_ 3
#define LW    49
#define NWIN  64
#define NWTOT (BATCH*NWIN)       // 2048
#define MTOK  (BATCH*LLEN)       // 100352

// ---------------- scratch ----------------
__device__ __nv_bfloat16 g_qkv [(size_t)MTOK*3*CCH];
__device__ __nv_bfloat16 g_attn[(size_t)MTOK*CCH];
__device__ __nv_bfloat16 g_h1  [(size_t)MTOK*4*CCH];
__device__ float g_xres[(size_t)MTOK*CCH];
__device__ float g_st1 [(size_t)MTOK*2];
__device__ float g_st2 [(size_t)MTOK*2];

__device__ __forceinline__ float gelu_exact(float x) {
    return 0.5f * x * (1.0f + erff(x * 0.70710678118654752f));
}
__device__ __forceinline__ uint32_t pack_bf16x2(float lo, float hi) {
    uint32_t o;
    asm("cvt.rn.bf16x2.f32 %0, %1, %2;" : "=r"(o) : "f"(hi), "f"(lo));
    return o;
}
__device__ __forceinline__ void mma_bf16(float c[4], const uint32_t a[4], const uint32_t b[2]) {
    asm volatile(
        "mma.sync.aligned.m16n8k16.row.col.f32.bf16.bf16.f32 "
        "{%0,%1,%2,%3}, {%4,%5,%6,%7}, {%8,%9}, {%0,%1,%2,%3};"
        : "+f"(c[0]), "+f"(c[1]), "+f"(c[2]), "+f"(c[3])
        : "r"(a[0]), "r"(a[1]), "r"(a[2]), "r"(a[3]), "r"(b[0]), "r"(b[1]));
}

__device__ __forceinline__ int winrow_to_token(int wr) {
    const int w  = wr / LW, local = wr % LW;
    const int b  = w >> 6, wl = w & 63;
    const int hp = (wl >> 3)*WSZ + local/WSZ;
    const int wp = (wl & 7)*WSZ + local%WSZ;
    int h = hp + SHIFT_; if (h >= IMGH) h -= IMGH;
    int ww = wp + SHIFT_; if (ww >= IMGW) ww -= IMGW;
    return b*LLEN + h*IMGW + ww;
}

// ---------------- LN stats: one warp per token ----------------
__global__ void __launch_bounds__(256)
ln_stats_kernel(const float* __restrict__ in, float* __restrict__ stats)
{
    const int warp = (blockIdx.x * 256 + threadIdx.x) >> 5;
    const int lane = threadIdx.x & 31;
    if (warp >= MTOK) return;
    const float* p = in + (size_t)warp*CCH;
    float s = 0.f, s2 = 0.f;
    #pragma unroll
    for (int i = 0; i < 6; ++i) {
        const float v = p[lane + i*32];
        s += v; s2 += v*v;
    }
    #pragma unroll
    for (int off = 16; off > 0; off >>= 1) {
        s  += __shfl_down_sync(0xffffffff, s,  off);
        s2 += __shfl_down_sync(0xffffffff, s2, off);
    }
    if (lane == 0) {
        const float mean = s * (1.0f/CCH);
        const float var  = s2 * (1.0f/CCH) - mean*mean;
        stats[2*warp]   = mean;
        stats[2*warp+1] = rsqrtf(var + 1e-5f);
    }
}

// ---------------- BF16 TC GEMM, fused LN/gather A-ops and fused epilogues ----
// AOP: 0=plain, 1=LN(A), 2=LN(A)+window-gather rows   (AOP!=0 -> fp32 A)
// ACT: 0=none, 1=gelu
// WOP: 0=plain, 1=scatter rows + add residual
// A_BF: A stored bf16 (requires AOP==0) | O_BF: output bf16
#define RS 20
#define ABUF (128*RS)
#define BBUF (64*RS)
template<int AOP, int ACT, bool HAS_BIAS, bool HAS_RES, int WOP, bool A_BF, bool O_BF>
__global__ void __launch_bounds__(256)
gemm_tc(const void* __restrict__ Av, const float* __restrict__ W,
        const float* __restrict__ bias, const float* __restrict__ res,
        const float* __restrict__ stats,
        const float* __restrict__ gamma, const float* __restrict__ beta,
        void* __restrict__ outv, int M, int N, int K)
{
    const float* Af = (const float*)Av;
    const __nv_bfloat16* Ab = (const __nv_bfloat16*)Av;
    float* outf = (float*)outv;
    __nv_bfloat16* outb = (__nv_bfloat16*)outv;

    const int tid  = threadIdx.x;
    const int lane = tid & 31;
    const int warp = tid >> 5;
    const int warpM = warp & 3;
    const int warpN = warp >> 2;
    const int m0 = blockIdx.y * 128;
    const int n0 = blockIdx.x * 64;

    __shared__ uint32_t sA[2*ABUF];
    __shared__ uint32_t sB[2*BBUF];

    float acc[2][4][4];
    #pragma unroll
    for (int i = 0; i < 2; ++i)
        #pragma unroll
        for (int j = 0; j < 4; ++j)
            #pragma unroll
            for (int q = 0; q < 4; ++q) acc[i][j][q] = 0.f;

    // fp32-A mapping: 4 float4 per thread, rows tid>>3 (+32 per rep), k-off (tid&7)*4
    const int aK4 = (tid & 7) << 2;
    const int kw0 = (tid & 7) << 1;
    const int aR0 = tid >> 3;
    // bf16-A mapping: 2 uint4 per thread (16B = 8 bf16), rows tid>>2 (+64), elem-off (tid&3)*8
    const int bK8  = (tid & 3) << 3;   // element offset
    const int bKW  = (tid & 3) << 2;   // word offset in smem row
    const int bR0  = tid >> 2;

    const int laneR = lane >> 2;
    const int laneK = lane & 3;
    uint32_t* baseA = &sA[(warpM*32 + laneR)*RS + laneK];
    uint32_t* baseB = &sB[(warpN*32 + laneR)*RS + laneK];

    int aSrc[4];
    float aMean[4], aRstd[4];
    if (!A_BF) {
        #pragma unroll
        for (int r = 0; r < 4; ++r) {
            const int wr = m0 + aR0 + r*32;
            aSrc[r] = (AOP == 2) ? winrow_to_token(wr) : wr;
            if (AOP != 0) {
                aMean[r] = stats[2*aSrc[r]];
                aRstd[r] = stats[2*aSrc[r]+1];
            }
        }
    }

    float4 ra4[4];
    uint4  rab[2];
    float4 rb[2];

    #define LOAD_A(k0)                                                           \
    {                                                                            \
        if (A_BF) {                                                              \
            _Pragma("unroll")                                                    \
            for (int r = 0; r < 2; ++r)                                          \
                rab[r] = *reinterpret_cast<const uint4*>(                        \
                             &Ab[(size_t)(m0 + bR0 + r*64)*K + (k0) + bK8]);     \
        } else {                                                                 \
            _Pragma("unroll")                                                    \
            for (int r = 0; r < 4; ++r)                                          \
                ra4[r] = *reinterpret_cast<const float4*>(                       \
                             &Af[(size_t)aSrc[r]*K + (k0) + aK4]);               \
        }                                                                        \
    }
    #define LOAD_B(k0)                                                           \
    {                                                                            \
        _Pragma("unroll")                                                        \
        for (int r = 0; r < 2; ++r)                                              \
            rb[r] = *reinterpret_cast<const float4*>(                            \
                        &W[(size_t)(n0 + aR0 + r*32)*K + (k0) + aK4]);           \
    }
    #define STORE_TILE(stage, koff)                                              \
    {                                                                            \
        if (A_BF) {                                                              \
            _Pragma("unroll")                                                    \
            for (int r = 0; r < 2; ++r) {                                        \
                uint32_t* p = &sA[(stage)*ABUF + (bR0 + r*64)*RS + bKW];         \
                p[0] = rab[r].x; p[1] = rab[r].y;                                \
                p[2] = rab[r].z; p[3] = rab[r].w;                                \
            }                                                                    \
        } else {                                                                 \
            float4 gm4, bt4;                                                     \
            if (AOP != 0) {                                                      \
                gm4 = *reinterpret_cast<const float4*>(&gamma[(koff) + aK4]);    \
                bt4 = *reinterpret_cast<const float4*>(&beta [(koff) + aK4]);    \
            }                                                                    \
            _Pragma("unroll")                                                    \
            for (int r = 0; r < 4; ++r) {                                        \
                float vx = ra4[r].x, vy = ra4[r].y, vz = ra4[r].z, vw = ra4[r].w;\
                if (AOP != 0) {                                                  \
                    vx = (vx - aMean[r])*aRstd[r]*gm4.x + bt4.x;                 \
                    vy = (vy - aMean[r])*aRstd[r]*gm4.y + bt4.y;                 \
                    vz = (vz - aMean[r])*aRstd[r]*gm4.z + bt4.z;                 \
                    vw = (vw - aMean[r])*aRstd[r]*gm4.w + bt4.w;                 \
                }                                                                \
                uint32_t* p = &sA[(stage)*ABUF + (aR0 + r*32)*RS + kw0];         \
                p[0] = pack_bf16x2(vx, vy);                                      \
                p[1] = pack_bf16x2(vz, vw);                                      \
            }                                                                    \
        }                                                                        \
        _Pragma("unroll")                                                        \
        for (int r = 0; r < 2; ++r) {                                            \
            uint32_t* p = &sB[(stage)*BBUF + (aR0 + r*32)*RS + kw0];             \
            p[0] = pack_bf16x2(rb[r].x, rb[r].y);                                \
            p[1] = pack_bf16x2(rb[r].z, rb[r].w);                                \
        }                                                                        \
    }

    LOAD_A(0)
    LOAD_B(0)
    STORE_TILE(0, 0)

    const int ntiles = K >> 5;
    for (int t = 0; t < ntiles; ++t) {
        __syncthreads();
        const bool more = (t + 1 < ntiles);
        if (more) {
            const int k0 = (t+1) << 5;
            LOAD_A(k0)
            LOAD_B(k0)
        }

        const uint32_t* pA = baseA + (t & 1)*ABUF;
        const uint32_t* pB = baseB + (t & 1)*BBUF;
        #pragma unroll
        for (int ks = 0; ks < 2; ++ks) {
            uint32_t af[2][4], bf[4][2];
            #pragma unroll
            for (int mt = 0; mt < 2; ++mt) {
                const uint32_t* q = pA + mt*(16*RS) + ks*8;
                af[mt][0] = q[0];
                af[mt][1] = q[8*RS];
                af[mt][2] = q[4];
                af[mt][3] = q[8*RS + 4];
            }
            #pragma unroll
            for (int nt = 0; nt < 4; ++nt) {
                const uint32_t* q = pB + nt*(8*RS) + ks*8;
                bf[nt][0] = q[0];
                bf[nt][1] = q[4];
            }
            #pragma unroll
            for (int mt = 0; mt < 2; ++mt)
                #pragma unroll
                for (int nt = 0; nt < 4; ++nt)
                    mma_bf16(acc[mt][nt], af[mt], bf[nt]);
        }

        if (more) {
            const int st = (t + 1) & 1;
            const int k0u = (t+1) << 5;
            STORE_TILE(st, k0u)
        }
    }
    #undef LOAD_A
    #undef LOAD_B
    #undef STORE_TILE

    // epilogue
    #pragma unroll
    for (int mt = 0; mt < 2; ++mt) {
        #pragma unroll
        for (int nt = 0; nt < 4; ++nt) {
            const int col = n0 + warpN*32 + nt*8 + (laneK << 1);
            const float b0 = HAS_BIAS ? bias[col]   : 0.f;
            const float b1 = HAS_BIAS ? bias[col+1] : 0.f;
            #pragma unroll
            for (int half = 0; half < 2; ++half) {
                const int wr = m0 + warpM*32 + mt*16 + laneR + half*8;
                const int row = (WOP == 1) ? winrow_to_token(wr) : wr;
                float v0 = acc[mt][nt][half*2+0] + b0;
                float v1 = acc[mt][nt][half*2+1] + b1;
                if (ACT == 1) { v0 = gelu_exact(v0); v1 = gelu_exact(v1); }
                if (HAS_RES || WOP == 1) {
                    const float2 r2 = *reinterpret_cast<const float2*>(&res[(size_t)row*N + col]);
                    v0 += r2.x; v1 += r2.y;
                }
                if (O_BF) {
                    *reinterpret_cast<uint32_t*>(&outb[(size_t)row*N + col]) = pack_bf16x2(v0, v1);
                } else {
                    *reinterpret_cast<float2*>(&outf[(size_t)row*N + col]) = make_float2(v0, v1);
                }
            }
        }
    }
}

// ---------------- fused attention per (window, head) ----------------
__device__ __forceinline__ int regid(int p) { return (p < 49) ? 0 : ((p < 53) ? 1 : 2); }

__device__ __forceinline__ void bf8_to_smem(uint4 v, float* dst) {
    const __nv_bfloat162* b2 = reinterpret_cast<const __nv_bfloat162*>(&v);
    #pragma unroll
    for (int m = 0; m < 4; ++m) {
        const float2 f = __bfloat1622float2(b2[m]);
        dst[2*m]   = f.x;
        dst[2*m+1] = f.y;
    }
}

__global__ void __launch_bounds__(128)
attn_kernel(const float* __restrict__ rel_bias)
{
    const int h = blockIdx.x;
    const int w = blockIdx.y;
    const int tid = threadIdx.x;

    __shared__ float sQ[LW*33];
    __shared__ float sK[LW*33];
    __shared__ float sV[LW*32];
    __shared__ float sS[LW*LW];

    // vectorized Q/K/V loads: 8 bf16 per uint4; 196 uint4 per matrix
    for (int t = tid; t < LW*HDIM/8; t += 128) {
        const int i = t >> 2, blk = (t & 3) << 3;
        const size_t base = (size_t)(w*LW + i) * (3*CCH) + h*HDIM + blk;
        bf8_to_smem(*reinterpret_cast<const uint4*>(&g_qkv[base]),          &sQ[i*33 + blk]);
        bf8_to_smem(*reinterpret_cast<const uint4*>(&g_qkv[base + CCH]),    &sK[i*33 + blk]);
        bf8_to_smem(*reinterpret_cast<const uint4*>(&g_qkv[base + 2*CCH]),  &sV[i*32 + blk]);
    }
    __syncthreads();

    const int wl  = w & (NWIN-1);
    const int wh_ = wl >> 3, ww_ = wl & 7;
    for (int t = tid; t < LW*LW; t += 128) {
        const int i = t / LW, j = t % LW;
        const int ih = i / WSZ, iw = i % WSZ;
        const int jh = j / WSZ, jw = j % WSZ;
        const int idi = regid(wh_*WSZ + ih)*3 + regid(ww_*WSZ + iw);
        const int idj = regid(wh_*WSZ + jh)*3 + regid(ww_*WSZ + jw);
        float sval;
        if (idi != idj) {
            sval = -100.0f;
        } else {
            float acc = 0.f;
            #pragma unroll
            for (int d = 0; d < HDIM; ++d)
                acc += sQ[i*33 + d] * sK[j*33 + d];
            const int bidx = ((ih - jh + 6)*13 + (iw - jw + 6));
            sval = acc * 13.856406460551018f + rel_bias[bidx*NHEAD + h];
        }
        sS[i*LW + j] = sval;
    }
    __syncthreads();

    if (tid < LW) {
        float mx = -1e30f;
        #pragma unroll
        for (int j = 0; j < LW; ++j) mx = fmaxf(mx, sS[tid*LW + j]);
        float sum = 0.f;
        #pragma unroll
        for (int j = 0; j < LW; ++j) {
            const float e = expf(sS[tid*LW + j] - mx);
            sS[tid*LW + j] = e;
            sum += e;
        }
        const float inv = 1.0f / sum;
        #pragma unroll
        for (int j = 0; j < LW; ++j) sS[tid*LW + j] *= inv;
    }
    __syncthreads();

    // out = P @ V, 8 outputs per task, stored as one uint4 (8 bf16)
    for (int t = tid; t < LW*HDIM/8; t += 128) {
        const int i = t >> 2, blk = (t & 3) << 3;
        float acc[8];
        #pragma unroll
        for (int q = 0; q < 8; ++q) acc[q] = 0.f;
        for (int j = 0; j < LW; ++j) {
            const float p = sS[i*LW + j];
            #pragma unroll
            for (int q = 0; q < 8; ++q)
                acc[q] += p * sV[j*32 + blk + q];
        }
        uint4 o;
        o.x = pack_bf16x2(acc[0], acc[1]);
        o.y = pack_bf16x2(acc[2], acc[3]);
        o.z = pack_bf16x2(acc[4], acc[5]);
        o.w = pack_bf16x2(acc[6], acc[7]);
        *reinterpret_cast<uint4*>(&g_attn[(size_t)(w*LW + i)*CCH + h*HDIM + blk]) = o;
    }
}

// ---------------- launch ----------------
extern "C" void kernel_launch(void* const* d_in, const int* in_sizes, int n_in,
                              void* d_out, int out_size)
{
    const void* arr[20];
    int na = 0;
    for (int i = 0; i < n_in && na < 20; ++i)
        if (in_sizes[i] != 1) arr[na++] = d_in[i];
    const float* x     = (const float*)arr[0];
    const float* n1w   = (const float*)arr[3];
    const float* n1b   = (const float*)arr[4];
    const float* qkvw  = (const float*)arr[5];
    const float* relb  = (const float*)arr[6];
    const float* projw = (const float*)arr[7];
    const float* projb = (const float*)arr[8];
    const float* n2w   = (const float*)arr[9];
    const float* n2b   = (const float*)arr[10];
    const float* fc1w  = (const float*)arr[11];
    const float* fc1b  = (const float*)arr[12];
    const float* fc2w  = (const float*)arr[13];
    const float* fc2b  = (const float*)arr[14];
    float* out = (float*)d_out;

    void* p_qkv;  cudaGetSymbolAddress(&p_qkv,  g_qkv);
    void* p_attn; cudaGetSymbolAddress(&p_attn, g_attn);
    void* p_h1;   cudaGetSymbolAddress(&p_h1,   g_h1);
    float* p_xres; cudaGetSymbolAddress((void**)&p_xres, g_xres);
    float* p_st1;  cudaGetSymbolAddress((void**)&p_st1,  g_st1);
    float* p_st2;  cudaGetSymbolAddress((void**)&p_st2,  g_st2);

    // 1) LN1 stats
    ln_stats_kernel<<<MTOK/8, 256>>>(x, p_st1);

    // 2) QKV GEMM: fused LN1 + gather (fp32 A), bf16 out
    gemm_tc<2, 0, false, false, 0, false, true><<<dim3(576/64, MTOK/128), 256>>>(
        x, qkvw, nullptr, nullptr, p_st1, n1w, n1b, p_qkv, MTOK, 3*CCH, CCH);

    // 3) fused windowed attention (vectorized bf16 in/out)
    attn_kernel<<<dim3(NHEAD, NWTOT), 128>>>(relb);

    // 4) proj GEMM: bf16 A (uint4 loads), + bias + scatter + residual(x) -> fp32
    gemm_tc<0, 0, true, false, 1, true, false><<<dim3(192/64, MTOK/128), 256>>>(
        p_attn, projw, projb, x, nullptr, nullptr, nullptr, p_xres, MTOK, CCH, CCH);

    // 5) LN2 stats
    ln_stats_kernel<<<MTOK/8, 256>>>(p_xres, p_st2);

    // 6) fc1 GEMM: fused LN2 (fp32 A), + bias + gelu, bf16 out
    gemm_tc<1, 1, true, false, 0, false, true><<<dim3(768/64, MTOK/128), 256>>>(
        p_xres, fc1w, fc1b, nullptr, p_st2, n2w, n2b, p_h1, MTOK, 4*CCH, CCH);

    // 7) fc2 GEMM: bf16 A (uint4 loads), + bias + gelu (quirk) + residual -> d_out
    gemm_tc<0, 1, true, true, 0, true, false><<<dim3(192/64, MTOK/128), 256>>>(
        p_h1, fc2w, fc2b, p_xres, nullptr, nullptr, nullptr, out, MTOK, CCH, 4*CCH);

    (void)out_size;
}

// round 7
// speedup vs baseline: 1.9207x; 1.2282x over previous
#include <cuda_runtime.h>
#include <cuda_bf16.h>
#include <math.h>
#include <stdint.h>

// ---------------- static problem shape ----------------
#define BATCH 32
#define IMGH  56
#define IMGW  56
#define CCH   192
#define LLEN  (IMGH*IMGW)        // 3136
#define NHEAD 6
#define HDIM  32
#define WSZ   7
#define SHIFT_ 3
#define LW    49
#define NWIN  64
#define NWTOT (BATCH*NWIN)       // 2048
#define MTOK  (BATCH*LLEN)       // 100352

// bf16 weight buffer offsets (elements)
#define WB_QKV  0
#define WB_PROJ (WB_QKV + 3*CCH*CCH)            // 110592
#define WB_FC1  (WB_PROJ + CCH*CCH)             // 147456
#define WB_FC2  (WB_FC1 + 4*CCH*CCH)            // 294912
#define WB_TOT  (WB_FC2 + 4*CCH*CCH)            // 442368

// ---------------- scratch ----------------
__device__ __nv_bfloat16 g_ln1 [(size_t)MTOK*CCH];
__device__ __nv_bfloat16 g_ln2 [(size_t)MTOK*CCH];
__device__ __nv_bfloat16 g_qkv [(size_t)MTOK*3*CCH];
__device__ __nv_bfloat16 g_attn[(size_t)MTOK*CCH];
__device__ __nv_bfloat16 g_h1  [(size_t)MTOK*4*CCH];
__device__ __nv_bfloat16 g_wb  [WB_TOT];
__device__ float g_xres[(size_t)MTOK*CCH];

__device__ __forceinline__ float gelu_exact(float x) {
    return 0.5f * x * (1.0f + erff(x * 0.70710678118654752f));
}
__device__ __forceinline__ uint32_t pack_bf16x2(float lo, float hi) {
    uint32_t o;
    asm("cvt.rn.bf16x2.f32 %0, %1, %2;" : "=r"(o) : "f"(hi), "f"(lo));
    return o;
}
__device__ __forceinline__ void mma_bf16(float c[4], const uint32_t a[4], const uint32_t b[2]) {
    asm volatile(
        "mma.sync.aligned.m16n8k16.row.col.f32.bf16.bf16.f32 "
        "{%0,%1,%2,%3}, {%4,%5,%6,%7}, {%8,%9}, {%0,%1,%2,%3};"
        : "+f"(c[0]), "+f"(c[1]), "+f"(c[2]), "+f"(c[3])
        : "r"(a[0]), "r"(a[1]), "r"(a[2]), "r"(a[3]), "r"(b[0]), "r"(b[1]));
}
__device__ __forceinline__ void cp_async16(uint32_t smem_addr, const void* gptr) {
    asm volatile("cp.async.cg.shared.global [%0], [%1], 16;" :: "r"(smem_addr), "l"(gptr));
}
__device__ __forceinline__ void cp_commit() { asm volatile("cp.async.commit_group;"); }
template<int N_> __device__ __forceinline__ void cp_wait() {
    asm volatile("cp.async.wait_group %0;" :: "n"(N_));
}

__device__ __forceinline__ int winrow_to_token(int wr) {
    const int w  = wr / LW, local = wr % LW;
    const int b  = w >> 6, wl = w & 63;
    const int hp = (wl >> 3)*WSZ + local/WSZ;
    const int wp = (wl & 7)*WSZ + local%WSZ;
    int h = hp + SHIFT_; if (h >= IMGH) h -= IMGH;
    int ww = wp + SHIFT_; if (ww >= IMGW) ww -= IMGW;
    return b*LLEN + h*IMGW + ww;
}

// ---------------- weight fp32 -> bf16 conversion (once per launch) ----------------
__global__ void __launch_bounds__(256)
wconv_kernel(const float* __restrict__ w0, const float* __restrict__ w1,
             const float* __restrict__ w2, const float* __restrict__ w3)
{
    const int i = blockIdx.x*256 + threadIdx.x;      // float4 index
    const int n0 = 3*CCH*CCH/4, n1 = CCH*CCH/4, n2 = CCH*CCH;  // n2 = 4*CCH*CCH/4
    const float* src; int local; size_t off;
    if (i < n0)                { src = w0; local = i;            off = WB_QKV; }
    else if (i < n0+n1)        { src = w1; local = i - n0;       off = WB_PROJ; }
    else if (i < n0+n1+n2)     { src = w2; local = i - n0 - n1;  off = WB_FC1; }
    else if (i < n0+n1+2*n2)   { src = w3; local = i - n0-n1-n2; off = WB_FC2; }
    else return;
    const float4 v = reinterpret_cast<const float4*>(src)[local];
    uint2 o;
    o.x = pack_bf16x2(v.x, v.y);
    o.y = pack_bf16x2(v.z, v.w);
    *reinterpret_cast<uint2*>(&g_wb[off + (size_t)local*4]) = o;
}

// ---------------- LayerNorm: stats + normalize + bf16 store, warp per token ----------------
__global__ void __launch_bounds__(256)
ln_norm_kernel(const float* __restrict__ in,
               const float* __restrict__ gamma, const float* __restrict__ beta,
               __nv_bfloat16* __restrict__ out)
{
    const int tok  = blockIdx.x*8 + (threadIdx.x >> 5);
    const int lane = threadIdx.x & 31;
    const float* p = in + (size_t)tok*CCH;

    float2 v[3];
    float s = 0.f, s2 = 0.f;
    #pragma unroll
    for (int i = 0; i < 3; ++i) {
        v[i] = *reinterpret_cast<const float2*>(&p[2*lane + 64*i]);
        s  += v[i].x + v[i].y;
        s2 += v[i].x*v[i].x + v[i].y*v[i].y;
    }
    #pragma unroll
    for (int off = 16; off > 0; off >>= 1) {
        s  += __shfl_xor_sync(0xffffffff, s,  off);
        s2 += __shfl_xor_sync(0xffffffff, s2, off);
    }
    const float mean = s * (1.0f/CCH);
    const float rstd = rsqrtf(s2 * (1.0f/CCH) - mean*mean + 1e-5f);

    #pragma unroll
    for (int i = 0; i < 3; ++i) {
        const float2 g = *reinterpret_cast<const float2*>(&gamma[2*lane + 64*i]);
        const float2 b = *reinterpret_cast<const float2*>(&beta [2*lane + 64*i]);
        const float y0 = (v[i].x - mean)*rstd*g.x + b.x;
        const float y1 = (v[i].y - mean)*rstd*g.y + b.y;
        *reinterpret_cast<uint32_t*>(&out[(size_t)tok*CCH + 2*lane + 64*i]) = pack_bf16x2(y0, y1);
    }
}

// ---------------- BF16 TC GEMM, cp.async 3-stage pipeline ----------------
// A[M,K] bf16, B[N,K] bf16. BM=128, BN=64, BK=32; 8 warps (4Mx2N), warp tile 32x32.
// GATHER: A rows gathered via winrow_to_token. SCATTER: out rows scattered + residual.
#define RS 20
#define ABUF (128*RS)
#define BBUF (64*RS)
template<int ACT, bool HAS_BIAS, bool HAS_RES, bool GATHER, bool SCATTER, bool O_BF>
__global__ void __launch_bounds__(256)
gemm_tc(const __nv_bfloat16* __restrict__ A, const __nv_bfloat16* __restrict__ B,
        const float* __restrict__ bias, const float* __restrict__ res,
        void* __restrict__ outv, int M, int N, int K)
{
    float* outf = (float*)outv;
    __nv_bfloat16* outb = (__nv_bfloat16*)outv;

    const int tid  = threadIdx.x;
    const int lane = tid & 31;
    const int warp = tid >> 5;
    const int warpM = warp & 3;
    const int warpN = warp >> 2;
    const int m0 = blockIdx.y * 128;
    const int n0 = blockIdx.x * 64;

    __shared__ uint32_t sA[3*ABUF];
    __shared__ uint32_t sB[3*BBUF];

    float acc[2][4][4];
    #pragma unroll
    for (int i = 0; i < 2; ++i)
        #pragma unroll
        for (int j = 0; j < 4; ++j)
            #pragma unroll
            for (int q = 0; q < 4; ++q) acc[i][j][q] = 0.f;

    // cp.async mapping: row = tid>>2 (A: +64 second row), 16B chunk = tid&3
    const int cRow  = tid >> 2;
    const int chunk = tid & 3;
    const int aSrc0 = GATHER ? winrow_to_token(m0 + cRow)      : m0 + cRow;
    const int aSrc1 = GATHER ? winrow_to_token(m0 + cRow + 64) : m0 + cRow + 64;

    const uint32_t saB = (uint32_t)__cvta_generic_to_shared(&sA[cRow*RS + chunk*4]);
    const uint32_t sbB = (uint32_t)__cvta_generic_to_shared(&sB[cRow*RS + chunk*4]);
    const __nv_bfloat16* pa0 = &A[(size_t)aSrc0*K + chunk*8];
    const __nv_bfloat16* pa1 = &A[(size_t)aSrc1*K + chunk*8];
    const __nv_bfloat16* pb  = &B[(size_t)(n0 + cRow)*K + chunk*8];

    #define ISSUE(s, k0)                                            \
    {                                                               \
        cp_async16(saB + (s)*(ABUF*4),              pa0 + (k0));    \
        cp_async16(saB + (s)*(ABUF*4) + 64*RS*4,    pa1 + (k0));    \
        cp_async16(sbB + (s)*(BBUF*4),              pb  + (k0));    \
        cp_commit();                                                \
    }

    ISSUE(0, 0)
    ISSUE(1, 32)

    const int laneR = lane >> 2;
    const int laneK = lane & 3;
    const uint32_t* baseA = &sA[(warpM*32 + laneR)*RS + laneK];
    const uint32_t* baseB = &sB[(warpN*32 + laneR)*RS + laneK];

    const int ntiles = K >> 5;
    int st = 0;
    for (int t = 0; t < ntiles; ++t) {
        if (t < ntiles - 1) cp_wait<1>(); else cp_wait<0>();
        __syncthreads();
        if (t + 2 < ntiles) {
            const int s2 = (st + 2 >= 3) ? st - 1 : st + 2;
            ISSUE(s2, (t+2)*32)
        }

        const uint32_t* pA = baseA + st*ABUF;
        const uint32_t* pB2 = baseB + st*BBUF;
        #pragma unroll
        for (int ks = 0; ks < 2; ++ks) {
            uint32_t af[2][4], bf[4][2];
            #pragma unroll
            for (int mt = 0; mt < 2; ++mt) {
                const uint32_t* q = pA + mt*(16*RS) + ks*8;
                af[mt][0] = q[0];
                af[mt][1] = q[8*RS];
                af[mt][2] = q[4];
                af[mt][3] = q[8*RS + 4];
            }
            #pragma unroll
            for (int nt = 0; nt < 4; ++nt) {
                const uint32_t* q = pB2 + nt*(8*RS) + ks*8;
                bf[nt][0] = q[0];
                bf[nt][1] = q[4];
            }
            #pragma unroll
            for (int mt = 0; mt < 2; ++mt)
                #pragma unroll
                for (int nt = 0; nt < 4; ++nt)
                    mma_bf16(acc[mt][nt], af[mt], bf[nt]);
        }
        st = (st == 2) ? 0 : st + 1;
    }
    #undef ISSUE

    // epilogue
    #pragma unroll
    for (int mt = 0; mt < 2; ++mt) {
        #pragma unroll
        for (int nt = 0; nt < 4; ++nt) {
            const int col = n0 + warpN*32 + nt*8 + (laneK << 1);
            const float b0 = HAS_BIAS ? bias[col]   : 0.f;
            const float b1 = HAS_BIAS ? bias[col+1] : 0.f;
            #pragma unroll
            for (int half = 0; half < 2; ++half) {
                const int wr = m0 + warpM*32 + mt*16 + laneR + half*8;
                const int row = SCATTER ? winrow_to_token(wr) : wr;
                float v0 = acc[mt][nt][half*2+0] + b0;
                float v1 = acc[mt][nt][half*2+1] + b1;
                if (ACT == 1) { v0 = gelu_exact(v0); v1 = gelu_exact(v1); }
                if (HAS_RES || SCATTER) {
                    const float2 r2 = *reinterpret_cast<const float2*>(&res[(size_t)row*N + col]);
                    v0 += r2.x; v1 += r2.y;
                }
                if (O_BF) {
                    *reinterpret_cast<uint32_t*>(&outb[(size_t)row*N + col]) = pack_bf16x2(v0, v1);
                } else {
                    *reinterpret_cast<float2*>(&outf[(size_t)row*N + col]) = make_float2(v0, v1);
                }
            }
        }
    }
}

// ---------------- fused attention per (window, head) ----------------
__device__ __forceinline__ int regid(int p) { return (p < 49) ? 0 : ((p < 53) ? 1 : 2); }

__device__ __forceinline__ void bf8_to_smem(uint4 v, float* dst) {
    const __nv_bfloat162* b2 = reinterpret_cast<const __nv_bfloat162*>(&v);
    #pragma unroll
    for (int m = 0; m < 4; ++m) {
        const float2 f = __bfloat1622float2(b2[m]);
        dst[2*m]   = f.x;
        dst[2*m+1] = f.y;
    }
}

__global__ void __launch_bounds__(128)
attn_kernel(const float* __restrict__ rel_bias)
{
    const int h = blockIdx.x;
    const int w = blockIdx.y;
    const int tid = threadIdx.x;

    __shared__ float sQ[LW*33];
    __shared__ float sK[LW*33];
    __shared__ float sV[LW*32];
    __shared__ float sS[LW*LW];

    for (int t = tid; t < LW*HDIM/8; t += 128) {
        const int i = t >> 2, blk = (t & 3) << 3;
        const size_t base = (size_t)(w*LW + i) * (3*CCH) + h*HDIM + blk;
        bf8_to_smem(*reinterpret_cast<const uint4*>(&g_qkv[base]),         &sQ[i*33 + blk]);
        bf8_to_smem(*reinterpret_cast<const uint4*>(&g_qkv[base + CCH]),   &sK[i*33 + blk]);
        bf8_to_smem(*reinterpret_cast<const uint4*>(&g_qkv[base + 2*CCH]), &sV[i*32 + blk]);
    }
    __syncthreads();

    const int wl  = w & (NWIN-1);
    const int wh_ = wl >> 3, ww_ = wl & 7;
    for (int t = tid; t < LW*LW; t += 128) {
        const int i = t / LW, j = t % LW;
        const int ih = i / WSZ, iw = i % WSZ;
        const int jh = j / WSZ, jw = j % WSZ;
        const int idi = regid(wh_*WSZ + ih)*3 + regid(ww_*WSZ + iw);
        const int idj = regid(wh_*WSZ + jh)*3 + regid(ww_*WSZ + jw);
        float sval;
        if (idi != idj) {
            sval = -100.0f;
        } else {
            float acc = 0.f;
            #pragma unroll
            for (int d = 0; d < HDIM; ++d)
                acc += sQ[i*33 + d] * sK[j*33 + d];
            const int bidx = ((ih - jh + 6)*13 + (iw - jw + 6));
            sval = acc * 13.856406460551018f + rel_bias[bidx*NHEAD + h];
        }
        sS[i*LW + j] = sval;
    }
    __syncthreads();

    if (tid < LW) {
        float mx = -1e30f;
        #pragma unroll
        for (int j = 0; j < LW; ++j) mx = fmaxf(mx, sS[tid*LW + j]);
        float sum = 0.f;
        #pragma unroll
        for (int j = 0; j < LW; ++j) {
            const float e = expf(sS[tid*LW + j] - mx);
            sS[tid*LW + j] = e;
            sum += e;
        }
        const float inv = 1.0f / sum;
        #pragma unroll
        for (int j = 0; j < LW; ++j) sS[tid*LW + j] *= inv;
    }
    __syncthreads();

    for (int t = tid; t < LW*HDIM/8; t += 128) {
        const int i = t >> 2, blk = (t & 3) << 3;
        float acc[8];
        #pragma unroll
        for (int q = 0; q < 8; ++q) acc[q] = 0.f;
        for (int j = 0; j < LW; ++j) {
            const float p = sS[i*LW + j];
            #pragma unroll
            for (int q = 0; q < 8; ++q)
                acc[q] += p * sV[j*32 + blk + q];
        }
        uint4 o;
        o.x = pack_bf16x2(acc[0], acc[1]);
        o.y = pack_bf16x2(acc[2], acc[3]);
        o.z = pack_bf16x2(acc[4], acc[5]);
        o.w = pack_bf16x2(acc[6], acc[7]);
        *reinterpret_cast<uint4*>(&g_attn[(size_t)(w*LW + i)*CCH + h*HDIM + blk]) = o;
    }
}

// ---------------- launch ----------------
extern "C" void kernel_launch(void* const* d_in, const int* in_sizes, int n_in,
                              void* d_out, int out_size)
{
    const void* arr[20];
    int na = 0;
    for (int i = 0; i < n_in && na < 20; ++i)
        if (in_sizes[i] != 1) arr[na++] = d_in[i];
    const float* x     = (const float*)arr[0];
    const float* n1w   = (const float*)arr[3];
    const float* n1b   = (const float*)arr[4];
    const float* qkvw  = (const float*)arr[5];
    const float* relb  = (const float*)arr[6];
    const float* projw = (const float*)arr[7];
    const float* projb = (const float*)arr[8];
    const float* n2w   = (const float*)arr[9];
    const float* n2b   = (const float*)arr[10];
    const float* fc1w  = (const float*)arr[11];
    const float* fc1b  = (const float*)arr[12];
    const float* fc2w  = (const float*)arr[13];
    const float* fc2b  = (const float*)arr[14];
    float* out = (float*)d_out;

    __nv_bfloat16 *p_ln1, *p_ln2, *p_qkv, *p_attn, *p_h1, *p_wb;
    cudaGetSymbolAddress((void**)&p_ln1,  g_ln1);
    cudaGetSymbolAddress((void**)&p_ln2,  g_ln2);
    cudaGetSymbolAddress((void**)&p_qkv,  g_qkv);
    cudaGetSymbolAddress((void**)&p_attn, g_attn);
    cudaGetSymbolAddress((void**)&p_h1,   g_h1);
    cudaGetSymbolAddress((void**)&p_wb,   g_wb);
    float* p_xres; cudaGetSymbolAddress((void**)&p_xres, g_xres);

    // 0) weights -> bf16
    wconv_kernel<<<(WB_TOT/4 + 255)/256, 256>>>(qkvw, projw, fc1w, fc2w);

    // 1) LN1 -> bf16 (token layout)
    ln_norm_kernel<<<MTOK/8, 256>>>(x, n1w, n1b, p_ln1);

    // 2) QKV GEMM: gather window rows of ln1, bf16 out
    gemm_tc<0, false, false, true, false, true><<<dim3(576/64, MTOK/128), 256>>>(
        p_ln1, p_wb + WB_QKV, nullptr, nullptr, p_qkv, MTOK, 3*CCH, CCH);

    // 3) fused windowed attention
    attn_kernel<<<dim3(NHEAD, NWTOT), 128>>>(relb);

    // 4) proj GEMM: + bias + scatter + residual(x) -> fp32 g_xres
    gemm_tc<0, true, false, false, true, false><<<dim3(192/64, MTOK/128), 256>>>(
        p_attn, p_wb + WB_PROJ, projb, x, p_xres, MTOK, CCH, CCH);

    // 5) LN2 -> bf16
    ln_norm_kernel<<<MTOK/8, 256>>>(p_xres, n2w, n2b, p_ln2);

    // 6) fc1 GEMM: + bias + gelu, bf16 out
    gemm_tc<1, true, false, false, false, true><<<dim3(768/64, MTOK/128), 256>>>(
        p_ln2, p_wb + WB_FC1, fc1b, nullptr, p_h1, MTOK, 4*CCH, CCH);

    // 7) fc2 GEMM: + bias + gelu (quirk) + residual -> d_out fp32
    gemm_tc<1, true, true, false, false, false><<<dim3(192/64, MTOK/128), 256>>>(
        p_h1, p_wb + WB_FC2, fc2b, p_xres, out, MTOK, CCH, 4*CCH);

    (void)out_size;
}

// round 8
// speedup vs baseline: 2.4961x; 1.2996x over previous
#include <cuda_runtime.h>
#include <cuda_bf16.h>
#include <math.h>
#include <stdint.h>

// ---------------- static problem shape ----------------
#define BATCH 32
#define IMGH  56
#define IMGW  56
#define CCH   192
#define LLEN  (IMGH*IMGW)        // 3136
#define NHEAD 6
#define HDIM  32
#define WSZ   7
#define SHIFT_ 3
#define LW    49
#define NWIN  64
#define NWTOT (BATCH*NWIN)       // 2048
#define MTOK  (BATCH*LLEN)       // 100352
#define QKSCALE 13.856406460551018f

// bf16 weight buffer offsets (elements)
#define WB_QKV  0
#define WB_PROJ (WB_QKV + 3*CCH*CCH)
#define WB_FC1  (WB_PROJ + CCH*CCH)
#define WB_FC2  (WB_FC1 + 4*CCH*CCH)
#define WB_TOT  (WB_FC2 + 4*CCH*CCH)

// ---------------- scratch ----------------
__device__ __nv_bfloat16 g_ln1 [(size_t)MTOK*CCH];
__device__ __nv_bfloat16 g_ln2 [(size_t)MTOK*CCH];
__device__ __nv_bfloat16 g_qkv [(size_t)MTOK*3*CCH];
__device__ __nv_bfloat16 g_attn[(size_t)MTOK*CCH];
__device__ __nv_bfloat16 g_h1  [(size_t)MTOK*4*CCH];
__device__ __nv_bfloat16 g_wb  [WB_TOT];
__device__ float g_xres[(size_t)MTOK*CCH];
__device__ float g_btab[4*NHEAD*LW*LW];         // bias+mask table per pattern/head

__device__ __forceinline__ float gelu_exact(float x) {
    return 0.5f * x * (1.0f + erff(x * 0.70710678118654752f));
}
__device__ __forceinline__ uint32_t pack_bf16x2(float lo, float hi) {
    uint32_t o;
    asm("cvt.rn.bf16x2.f32 %0, %1, %2;" : "=r"(o) : "f"(hi), "f"(lo));
    return o;
}
__device__ __forceinline__ void mma_bf16(float c[4], const uint32_t a[4], const uint32_t b[2]) {
    asm volatile(
        "mma.sync.aligned.m16n8k16.row.col.f32.bf16.bf16.f32 "
        "{%0,%1,%2,%3}, {%4,%5,%6,%7}, {%8,%9}, {%0,%1,%2,%3};"
        : "+f"(c[0]), "+f"(c[1]), "+f"(c[2]), "+f"(c[3])
        : "r"(a[0]), "r"(a[1]), "r"(a[2]), "r"(a[3]), "r"(b[0]), "r"(b[1]));
}
__device__ __forceinline__ void cp_async16(uint32_t smem_addr, const void* gptr) {
    asm volatile("cp.async.cg.shared.global [%0], [%1], 16;" :: "r"(smem_addr), "l"(gptr));
}
__device__ __forceinline__ void cp_commit() { asm volatile("cp.async.commit_group;"); }
template<int N_> __device__ __forceinline__ void cp_wait() {
    asm volatile("cp.async.wait_group %0;" :: "n"(N_));
}

__device__ __forceinline__ int winrow_to_token(int wr) {
    const int w  = wr / LW, local = wr % LW;
    const int b  = w >> 6, wl = w & 63;
    const int hp = (wl >> 3)*WSZ + local/WSZ;
    const int wp = (wl & 7)*WSZ + local%WSZ;
    int h = hp + SHIFT_; if (h >= IMGH) h -= IMGH;
    int ww = wp + SHIFT_; if (ww >= IMGW) ww -= IMGW;
    return b*LLEN + h*IMGW + ww;
}
__device__ __forceinline__ int regid(int p) { return (p < 49) ? 0 : ((p < 53) ? 1 : 2); }

// ---------------- bias+mask table (once per launch) ----------------
__global__ void __launch_bounds__(256)
btab_kernel(const float* __restrict__ rel_bias)
{
    const int idx = blockIdx.x*256 + threadIdx.x;
    if (idx >= 4*NHEAD*LW*LW) return;
    const int j = idx % LW;
    const int i = (idx / LW) % LW;
    const int h = (idx / (LW*LW)) % NHEAD;
    const int p = idx / (NHEAD*LW*LW);
    const int wh = (p >> 1) ? 7 : 0;
    const int ww = (p & 1) ? 7 : 0;
    const int ih = i / WSZ, iw = i % WSZ;
    const int jh = j / WSZ, jw = j % WSZ;
    const int idi = regid(wh*WSZ + ih)*3 + regid(ww*WSZ + iw);
    const int idj = regid(wh*WSZ + jh)*3 + regid(ww*WSZ + jw);
    float v;
    if (idi != idj) v = -10000.0f;
    else            v = rel_bias[((ih - jh + 6)*13 + (iw - jw + 6))*NHEAD + h];
    g_btab[idx] = v;
}

// ---------------- weight fp32 -> bf16 conversion ----------------
__global__ void __launch_bounds__(256)
wconv_kernel(const float* __restrict__ w0, const float* __restrict__ w1,
             const float* __restrict__ w2, const float* __restrict__ w3)
{
    const int i = blockIdx.x*256 + threadIdx.x;
    const int n0 = 3*CCH*CCH/4, n1 = CCH*CCH/4, n2 = CCH*CCH;
    const float* src; int local; size_t off;
    if (i < n0)                { src = w0; local = i;            off = WB_QKV; }
    else if (i < n0+n1)        { src = w1; local = i - n0;       off = WB_PROJ; }
    else if (i < n0+n1+n2)     { src = w2; local = i - n0 - n1;  off = WB_FC1; }
    else if (i < n0+n1+2*n2)   { src = w3; local = i - n0-n1-n2; off = WB_FC2; }
    else return;
    const float4 v = reinterpret_cast<const float4*>(src)[local];
    uint2 o;
    o.x = pack_bf16x2(v.x, v.y);
    o.y = pack_bf16x2(v.z, v.w);
    *reinterpret_cast<uint2*>(&g_wb[off + (size_t)local*4]) = o;
}

// ---------------- LayerNorm: stats + normalize + bf16 store ----------------
__global__ void __launch_bounds__(256)
ln_norm_kernel(const float* __restrict__ in,
               const float* __restrict__ gamma, const float* __restrict__ beta,
               __nv_bfloat16* __restrict__ out)
{
    const int tok  = blockIdx.x*8 + (threadIdx.x >> 5);
    const int lane = threadIdx.x & 31;
    const float* p = in + (size_t)tok*CCH;

    float2 v[3];
    float s = 0.f, s2 = 0.f;
    #pragma unroll
    for (int i = 0; i < 3; ++i) {
        v[i] = *reinterpret_cast<const float2*>(&p[2*lane + 64*i]);
        s  += v[i].x + v[i].y;
        s2 += v[i].x*v[i].x + v[i].y*v[i].y;
    }
    #pragma unroll
    for (int off = 16; off > 0; off >>= 1) {
        s  += __shfl_xor_sync(0xffffffff, s,  off);
        s2 += __shfl_xor_sync(0xffffffff, s2, off);
    }
    const float mean = s * (1.0f/CCH);
    const float rstd = rsqrtf(s2 * (1.0f/CCH) - mean*mean + 1e-5f);

    #pragma unroll
    for (int i = 0; i < 3; ++i) {
        const float2 g = *reinterpret_cast<const float2*>(&gamma[2*lane + 64*i]);
        const float2 b = *reinterpret_cast<const float2*>(&beta [2*lane + 64*i]);
        const float y0 = (v[i].x - mean)*rstd*g.x + b.x;
        const float y1 = (v[i].y - mean)*rstd*g.y + b.y;
        *reinterpret_cast<uint32_t*>(&out[(size_t)tok*CCH + 2*lane + 64*i]) = pack_bf16x2(y0, y1);
    }
}

// ---------------- BF16 TC GEMM, cp.async 3-stage pipeline ----------------
#define RS 20
#define ABUF (128*RS)
#define BBUF (64*RS)
template<int ACT, bool HAS_BIAS, bool HAS_RES, bool GATHER, bool SCATTER, bool O_BF>
__global__ void __launch_bounds__(256)
gemm_tc(const __nv_bfloat16* __restrict__ A, const __nv_bfloat16* __restrict__ B,
        const float* __restrict__ bias, const float* __restrict__ res,
        void* __restrict__ outv, int M, int N, int K)
{
    float* outf = (float*)outv;
    __nv_bfloat16* outb = (__nv_bfloat16*)outv;

    const int tid  = threadIdx.x;
    const int lane = tid & 31;
    const int warp = tid >> 5;
    const int warpM = warp & 3;
    const int warpN = warp >> 2;
    const int m0 = blockIdx.y * 128;
    const int n0 = blockIdx.x * 64;

    __shared__ uint32_t sA[3*ABUF];
    __shared__ uint32_t sB[3*BBUF];

    float acc[2][4][4];
    #pragma unroll
    for (int i = 0; i < 2; ++i)
        #pragma unroll
        for (int j = 0; j < 4; ++j)
            #pragma unroll
            for (int q = 0; q < 4; ++q) acc[i][j][q] = 0.f;

    const int cRow  = tid >> 2;
    const int chunk = tid & 3;
    const int aSrc0 = GATHER ? winrow_to_token(m0 + cRow)      : m0 + cRow;
    const int aSrc1 = GATHER ? winrow_to_token(m0 + cRow + 64) : m0 + cRow + 64;

    const uint32_t saB = (uint32_t)__cvta_generic_to_shared(&sA[cRow*RS + chunk*4]);
    const uint32_t sbB = (uint32_t)__cvta_generic_to_shared(&sB[cRow*RS + chunk*4]);
    const __nv_bfloat16* pa0 = &A[(size_t)aSrc0*K + chunk*8];
    const __nv_bfloat16* pa1 = &A[(size_t)aSrc1*K + chunk*8];
    const __nv_bfloat16* pb  = &B[(size_t)(n0 + cRow)*K + chunk*8];

    #define ISSUE(s, k0)                                            \
    {                                                               \
        cp_async16(saB + (s)*(ABUF*4),              pa0 + (k0));    \
        cp_async16(saB + (s)*(ABUF*4) + 64*RS*4,    pa1 + (k0));    \
        cp_async16(sbB + (s)*(BBUF*4),              pb  + (k0));    \
        cp_commit();                                                \
    }

    ISSUE(0, 0)
    ISSUE(1, 32)

    const int laneR = lane >> 2;
    const int laneK = lane & 3;
    const uint32_t* baseA = &sA[(warpM*32 + laneR)*RS + laneK];
    const uint32_t* baseB = &sB[(warpN*32 + laneR)*RS + laneK];

    const int ntiles = K >> 5;
    int st = 0;
    for (int t = 0; t < ntiles; ++t) {
        if (t < ntiles - 1) cp_wait<1>(); else cp_wait<0>();
        __syncthreads();
        if (t + 2 < ntiles) {
            const int s2 = (st + 2 >= 3) ? st - 1 : st + 2;
            ISSUE(s2, (t+2)*32)
        }

        const uint32_t* pA = baseA + st*ABUF;
        const uint32_t* pB2 = baseB + st*BBUF;
        #pragma unroll
        for (int ks = 0; ks < 2; ++ks) {
            uint32_t af[2][4], bf[4][2];
            #pragma unroll
            for (int mt = 0; mt < 2; ++mt) {
                const uint32_t* q = pA + mt*(16*RS) + ks*8;
                af[mt][0] = q[0];
                af[mt][1] = q[8*RS];
                af[mt][2] = q[4];
                af[mt][3] = q[8*RS + 4];
            }
            #pragma unroll
            for (int nt = 0; nt < 4; ++nt) {
                const uint32_t* q = pB2 + nt*(8*RS) + ks*8;
                bf[nt][0] = q[0];
                bf[nt][1] = q[4];
            }
            #pragma unroll
            for (int mt = 0; mt < 2; ++mt)
                #pragma unroll
                for (int nt = 0; nt < 4; ++nt)
                    mma_bf16(acc[mt][nt], af[mt], bf[nt]);
        }
        st = (st == 2) ? 0 : st + 1;
    }
    #undef ISSUE

    #pragma unroll
    for (int mt = 0; mt < 2; ++mt) {
        #pragma unroll
        for (int nt = 0; nt < 4; ++nt) {
            const int col = n0 + warpN*32 + nt*8 + (laneK << 1);
            const float b0 = HAS_BIAS ? bias[col]   : 0.f;
            const float b1 = HAS_BIAS ? bias[col+1] : 0.f;
            #pragma unroll
            for (int half = 0; half < 2; ++half) {
                const int wr = m0 + warpM*32 + mt*16 + laneR + half*8;
                const int row = SCATTER ? winrow_to_token(wr) : wr;
                float v0 = acc[mt][nt][half*2+0] + b0;
                float v1 = acc[mt][nt][half*2+1] + b1;
                if (ACT == 1) { v0 = gelu_exact(v0); v1 = gelu_exact(v1); }
                if (HAS_RES || SCATTER) {
                    const float2 r2 = *reinterpret_cast<const float2*>(&res[(size_t)row*N + col]);
                    v0 += r2.x; v1 += r2.y;
                }
                if (O_BF) {
                    *reinterpret_cast<uint32_t*>(&outb[(size_t)row*N + col]) = pack_bf16x2(v0, v1);
                } else {
                    *reinterpret_cast<float2*>(&outf[(size_t)row*N + col]) = make_float2(v0, v1);
                }
            }
        }
    }
}

// ---------------- fused attention, register-tiled, table-driven bias ----------------
__device__ __forceinline__ void bf8_to_smem_s(uint4 v, float* dst, float scale) {
    const __nv_bfloat162* b2 = reinterpret_cast<const __nv_bfloat162*>(&v);
    #pragma unroll
    for (int m = 0; m < 4; ++m) {
        const float2 f = __bfloat1622float2(b2[m]);
        dst[2*m]   = f.x * scale;
        dst[2*m+1] = f.y * scale;
    }
}

#define SSTR 52
__global__ void __launch_bounds__(128)
attn_kernel()
{
    const int h = blockIdx.x;
    const int w = blockIdx.y;
    const int tid = threadIdx.x;

    __shared__ float sQ[56*33];    // rows 49..55 uninit (never used for output)
    __shared__ float sK[64*33];    // rows 49..63 uninit
    __shared__ float sV[LW*32];
    __shared__ float sS[LW*SSTR];

    // load Q (scaled), K, V; 8 bf16 per uint4
    for (int t = tid; t < LW*HDIM/8; t += 128) {
        const int i = t >> 2, blk = (t & 3) << 3;
        const size_t base = (size_t)(w*LW + i) * (3*CCH) + h*HDIM + blk;
        bf8_to_smem_s(*reinterpret_cast<const uint4*>(&g_qkv[base]),         &sQ[i*33 + blk], QKSCALE);
        bf8_to_smem_s(*reinterpret_cast<const uint4*>(&g_qkv[base + CCH]),   &sK[i*33 + blk], 1.0f);
        bf8_to_smem_s(*reinterpret_cast<const uint4*>(&g_qkv[base + 2*CCH]), &sV[i*32 + blk], 1.0f);
    }
    __syncthreads();

    // QK^T register-tiled: thread = (ti 0..7, tj 0..15), tile 7 rows x 4 cols
    {
        const int ti = tid >> 4, tj = tid & 15;
        const int r0 = ti*7, c0 = tj*4;
        float acc[7][4];
        #pragma unroll
        for (int r = 0; r < 7; ++r)
            #pragma unroll
            for (int c = 0; c < 4; ++c) acc[r][c] = 0.f;
        #pragma unroll
        for (int d = 0; d < HDIM; ++d) {
            float kv[4];
            #pragma unroll
            for (int c = 0; c < 4; ++c) kv[c] = sK[(c0 + c)*33 + d];
            #pragma unroll
            for (int r = 0; r < 7; ++r) {
                const float qv = sQ[(r0 + r)*33 + d];
                #pragma unroll
                for (int c = 0; c < 4; ++c) acc[r][c] += qv * kv[c];
            }
        }
        const int wl  = w & (NWIN-1);
        const int pat = (((wl >> 3) == 7) ? 2 : 0) + (((wl & 7) == 7) ? 1 : 0);
        const float* bt = g_btab + (size_t)(pat*NHEAD + h)*LW*LW;
        #pragma unroll
        for (int r = 0; r < 7; ++r) {
            const int row = r0 + r;
            if (row < LW) {
                #pragma unroll
                for (int c = 0; c < 4; ++c) {
                    const int col = c0 + c;
                    if (col < LW)
                        sS[row*SSTR + col] = acc[r][c] + bt[row*LW + col];
                }
            }
        }
    }
    __syncthreads();

    // softmax (one thread per row)
    if (tid < LW) {
        float* row = &sS[tid*SSTR];
        float mx = -1e30f;
        #pragma unroll
        for (int j = 0; j < LW; ++j) mx = fmaxf(mx, row[j]);
        float sum = 0.f;
        #pragma unroll
        for (int j = 0; j < LW; ++j) {
            const float e = __expf(row[j] - mx);
            row[j] = e;
            sum += e;
        }
        const float inv = 1.0f / sum;
        #pragma unroll
        for (int j = 0; j < LW; ++j) row[j] *= inv;
    }
    __syncthreads();

    // PV register-tiled: thread = (r0 = tid>>2 rows {r0, r0+32}, dblk = (tid&3)*8)
    {
        const int r0 = tid >> 2;
        const int r1 = r0 + 32;
        const int db = (tid & 3) << 3;
        float a0[8], a1[8];
        #pragma unroll
        for (int q = 0; q < 8; ++q) { a0[q] = 0.f; a1[q] = 0.f; }
        const bool has1 = (r1 < LW);
        for (int j = 0; j < LW; ++j) {
            const float p0 = sS[r0*SSTR + j];
            const float p1 = has1 ? sS[r1*SSTR + j] : 0.f;
            #pragma unroll
            for (int q = 0; q < 8; ++q) {
                const float vv = sV[j*32 + db + q];
                a0[q] += p0 * vv;
                a1[q] += p1 * vv;
            }
        }
        uint4 o;
        o.x = pack_bf16x2(a0[0], a0[1]);
        o.y = pack_bf16x2(a0[2], a0[3]);
        o.z = pack_bf16x2(a0[4], a0[5]);
        o.w = pack_bf16x2(a0[6], a0[7]);
        *reinterpret_cast<uint4*>(&g_attn[(size_t)(w*LW + r0)*CCH + h*HDIM + db]) = o;
        if (has1) {
            uint4 o1;
            o1.x = pack_bf16x2(a1[0], a1[1]);
            o1.y = pack_bf16x2(a1[2], a1[3]);
            o1.z = pack_bf16x2(a1[4], a1[5]);
            o1.w = pack_bf16x2(a1[6], a1[7]);
            *reinterpret_cast<uint4*>(&g_attn[(size_t)(w*LW + r1)*CCH + h*HDIM + db]) = o1;
        }
    }
}

// ---------------- launch ----------------
extern "C" void kernel_launch(void* const* d_in, const int* in_sizes, int n_in,
                              void* d_out, int out_size)
{
    const void* arr[20];
    int na = 0;
    for (int i = 0; i < n_in && na < 20; ++i)
        if (in_sizes[i] != 1) arr[na++] = d_in[i];
    const float* x     = (const float*)arr[0];
    const float* n1w   = (const float*)arr[3];
    const float* n1b   = (const float*)arr[4];
    const float* qkvw  = (const float*)arr[5];
    const float* relb  = (const float*)arr[6];
    const float* projw = (const float*)arr[7];
    const float* projb = (const float*)arr[8];
    const float* n2w   = (const float*)arr[9];
    const float* n2b   = (const float*)arr[10];
    const float* fc1w  = (const float*)arr[11];
    const float* fc1b  = (const float*)arr[12];
    const float* fc2w  = (const float*)arr[13];
    const float* fc2b  = (const float*)arr[14];
    float* out = (float*)d_out;

    __nv_bfloat16 *p_ln1, *p_ln2, *p_qkv, *p_attn, *p_h1, *p_wb;
    cudaGetSymbolAddress((void**)&p_ln1,  g_ln1);
    cudaGetSymbolAddress((void**)&p_ln2,  g_ln2);
    cudaGetSymbolAddress((void**)&p_qkv,  g_qkv);
    cudaGetSymbolAddress((void**)&p_attn, g_attn);
    cudaGetSymbolAddress((void**)&p_h1,   g_h1);
    cudaGetSymbolAddress((void**)&p_wb,   g_wb);
    float* p_xres; cudaGetSymbolAddress((void**)&p_xres, g_xres);

    // 0) weights -> bf16 ; bias+mask table
    wconv_kernel<<<(WB_TOT/4 + 255)/256, 256>>>(qkvw, projw, fc1w, fc2w);
    btab_kernel<<<(4*NHEAD*LW*LW + 255)/256, 256>>>(relb);

    // 1) LN1 -> bf16
    ln_norm_kernel<<<MTOK/8, 256>>>(x, n1w, n1b, p_ln1);

    // 2) QKV GEMM (gather), bf16 out
    gemm_tc<0, false, false, true, false, true><<<dim3(576/64, MTOK/128), 256>>>(
        p_ln1, p_wb + WB_QKV, nullptr, nullptr, p_qkv, MTOK, 3*CCH, CCH);

    // 3) fused windowed attention
    attn_kernel<<<dim3(NHEAD, NWTOT), 128>>>();

    // 4) proj GEMM: + bias + scatter + residual(x) -> fp32 g_xres
    gemm_tc<0, true, false, false, true, false><<<dim3(192/64, MTOK/128), 256>>>(
        p_attn, p_wb + WB_PROJ, projb, x, p_xres, MTOK, CCH, CCH);

    // 5) LN2 -> bf16
    ln_norm_kernel<<<MTOK/8, 256>>>(p_xres, n2w, n2b, p_ln2);

    // 6) fc1 GEMM: + bias + gelu, bf16 out
    gemm_tc<1, true, false, false, false, true><<<dim3(768/64, MTOK/128), 256>>>(
        p_ln2, p_wb + WB_FC1, fc1b, nullptr, p_h1, MTOK, 4*CCH, CCH);

    // 7) fc2 GEMM: + bias + gelu (quirk) + residual -> d_out fp32
    gemm_tc<1, true, true, false, false, false><<<dim3(192/64, MTOK/128), 256>>>(
        p_h1, p_wb + WB_FC2, fc2b, p_xres, out, MTOK, CCH, 4*CCH);

    (void)out_size;
}